// round 9
// baseline (speedup 1.0000x reference)
#include <cuda_runtime.h>
#include <cuda_bf16.h>
#include <cstdint>

#define NN 50000
#define EE 800000
#define DD 128
#define TMAGG 64                 // nodes per block, aggregation kernel
#define TMMLP 128                // nodes per block, MMA kernel
#define SAU 68                   // smem A row stride in u32 (136 bf16)

// ---- scratch (__device__ globals; no allocs allowed) ----------------------
__device__ int  g_deg[NN];
__device__ int  g_cursor[NN];
__device__ int  g_off[NN + 1];
__device__ int2 g_edge[EE];                    // (src, attr bits)
__device__ uint32_t g_h0h[NN * 64];            // h0 hi, bf16x2 packed
__device__ uint32_t g_h0l[NN * 64];            // h0 lo
__device__ uint32_t g_W1h[DD * 64], g_W1l[DD * 64];   // Wt[n][k] bf16x2 (k-pairs)
__device__ uint32_t g_W2h[DD * 64], g_W2l[DD * 64];

// ---------------------------------------------------------------------------
__global__ void zero_kernel() {
    int i = blockIdx.x * blockDim.x + threadIdx.x;
    if (i < NN) g_deg[i] = 0;
}

__global__ __launch_bounds__(256) void hist_kernel(const int* __restrict__ ei) {
    int e = blockIdx.x * blockDim.x + threadIdx.x;
    if (e >= EE) return;
    atomicAdd(&g_deg[__ldg(&ei[EE + e])], 1);
}

__global__ __launch_bounds__(1024) void scan_kernel() {
    __shared__ int wsum[32];
    __shared__ int carry_sh;
    const int lane = threadIdx.x & 31;
    const int wid  = threadIdx.x >> 5;
    if (threadIdx.x == 0) carry_sh = 0;
    __syncthreads();
    for (int base = 0; base < NN; base += 1024) {
        int i = base + threadIdx.x;
        int v = (i < NN) ? g_deg[i] : 0;
        int orig = v;
        #pragma unroll
        for (int off = 1; off < 32; off <<= 1) {
            int t = __shfl_up_sync(0xffffffffu, v, off);
            if (lane >= off) v += t;
        }
        if (lane == 31) wsum[wid] = v;
        __syncthreads();
        if (wid == 0) {
            int s = wsum[lane];
            #pragma unroll
            for (int off = 1; off < 32; off <<= 1) {
                int t = __shfl_up_sync(0xffffffffu, s, off);
                if (lane >= off) s += t;
            }
            wsum[lane] = s;
        }
        __syncthreads();
        int warp_prefix = (wid > 0) ? wsum[wid - 1] : 0;
        int carry = carry_sh;
        if (i < NN) {
            int excl = carry + warp_prefix + v - orig;
            g_off[i] = excl;
            g_cursor[i] = excl;
        }
        __syncthreads();
        if (threadIdx.x == 1023) carry_sh = carry + wsum[31];
        __syncthreads();
    }
    if (threadIdx.x == 0) g_off[NN] = carry_sh;
}

__global__ __launch_bounds__(256) void fill_kernel(
    const int* __restrict__ ei, const float* __restrict__ ea)
{
    int e = blockIdx.x * blockDim.x + threadIdx.x;
    if (e >= EE) return;
    int src = __ldg(&ei[e]);
    int dst = __ldg(&ei[EE + e]);
    int slot = atomicAdd(&g_cursor[dst], 1);
    g_edge[slot] = make_int2(src, __float_as_int(__ldg(&ea[e])));
}

// ---------------------------------------------------------------------------
// weight split+transpose: W[k][n] f32 -> Wt[n][k] hi/lo bf16 (packed k-pairs)
// ---------------------------------------------------------------------------
__device__ __forceinline__ uint32_t pack2(float a, float b) {
    __nv_bfloat16 ha = __float2bfloat16(a), hb = __float2bfloat16(b);
    return ((uint32_t)__bfloat16_as_ushort(hb) << 16) | __bfloat16_as_ushort(ha);
}

__global__ __launch_bounds__(256) void wsplit_kernel(
    const float* __restrict__ W1, const float* __restrict__ W2)
{
    int i = blockIdx.x * blockDim.x + threadIdx.x;   // 8192 k-pairs
    if (i >= DD * 64) return;
    int n = i >> 6;
    int k = (i & 63) * 2;
    float a0 = __ldg(&W1[(size_t)k * DD + n]);
    float a1 = __ldg(&W1[(size_t)(k + 1) * DD + n]);
    float b0 = __ldg(&W2[(size_t)k * DD + n]);
    float b1 = __ldg(&W2[(size_t)(k + 1) * DD + n]);
    float ah0 = __bfloat162float(__float2bfloat16(a0));
    float ah1 = __bfloat162float(__float2bfloat16(a1));
    float bh0 = __bfloat162float(__float2bfloat16(b0));
    float bh1 = __bfloat162float(__float2bfloat16(b1));
    g_W1h[i] = pack2(ah0, ah1);
    g_W1l[i] = pack2(a0 - ah0, a1 - ah1);
    g_W2h[i] = pack2(bh0, bh1);
    g_W2l[i] = pack2(b0 - bh0, b1 - bh1);
}

// ---------------------------------------------------------------------------
// aggregation: CSR mean-aggregate + (1+eps)*h, write split bf16 h0 to global
// warp-per-node, 8 nodes/warp, 64 nodes/block
// ---------------------------------------------------------------------------
__global__ __launch_bounds__(256) void agg_kernel(
    const float* __restrict__ hidden,
    const float* __restrict__ We, const float* __restrict__ be,
    const float* __restrict__ eps)
{
    const int lane = threadIdx.x & 31;
    const int wid  = threadIdx.x >> 5;
    const int base = blockIdx.x * TMAGG;
    const float epsv = 1.0f + __ldg(eps);

    const float4* h4 = reinterpret_cast<const float4*>(hidden);
    float4 w = __ldg(&reinterpret_cast<const float4*>(We)[lane]);
    float4 b = __ldg(&reinterpret_cast<const float4*>(be)[lane]);

    #pragma unroll 1
    for (int j = 0; j < 8; j++) {
        int n = base + wid * 8 + j;
        if (n >= NN) return;
        int s0 = __ldg(&g_off[n]);
        int s1 = __ldg(&g_off[n + 1]);
        float4 acc = make_float4(0.f, 0.f, 0.f, 0.f);
        #pragma unroll 4
        for (int s = s0; s < s1; s++) {
            int2 e = __ldg(&g_edge[s]);
            float a = __int_as_float(e.y);
            float4 h = __ldg(&h4[(size_t)e.x * 32 + lane]);
            acc.x += fmaxf(h.x + fmaf(a, w.x, b.x), 0.f);
            acc.y += fmaxf(h.y + fmaf(a, w.y, b.y), 0.f);
            acc.z += fmaxf(h.z + fmaf(a, w.z, b.z), 0.f);
            acc.w += fmaxf(h.w + fmaf(a, w.w, b.w), 0.f);
        }
        float inv = 1.0f / fmaxf((float)(s1 - s0), 1.0f);
        float4 hv = __ldg(&h4[(size_t)n * 32 + lane]);
        float4 v;
        v.x = fmaf(epsv, hv.x, acc.x * inv);
        v.y = fmaf(epsv, hv.y, acc.y * inv);
        v.z = fmaf(epsv, hv.z, acc.z * inv);
        v.w = fmaf(epsv, hv.w, acc.w * inv);
        float hx = __bfloat162float(__float2bfloat16(v.x));
        float hy = __bfloat162float(__float2bfloat16(v.y));
        float hz = __bfloat162float(__float2bfloat16(v.z));
        float hw = __bfloat162float(__float2bfloat16(v.w));
        size_t o = (size_t)n * 64 + 2 * lane;
        g_h0h[o]     = pack2(hx, hy);
        g_h0h[o + 1] = pack2(hz, hw);
        g_h0l[o]     = pack2(v.x - hx, v.y - hy);
        g_h0l[o + 1] = pack2(v.z - hz, v.w - hw);
    }
}

// ---------------------------------------------------------------------------
// mma.sync bf16 split-precision MLP: relu(h0@W1+b1)@W2+b2
// 256 threads = 8 warps, 16 rows/warp, 128 rows/CTA
// ---------------------------------------------------------------------------
__device__ __forceinline__ void mma_bf16(float* c, const uint32_t* a,
                                         uint32_t b0, uint32_t b1) {
    asm volatile(
        "mma.sync.aligned.m16n8k16.row.col.f32.bf16.bf16.f32 "
        "{%0,%1,%2,%3}, {%4,%5,%6,%7}, {%8,%9}, {%0,%1,%2,%3};"
        : "+f"(c[0]), "+f"(c[1]), "+f"(c[2]), "+f"(c[3])
        : "r"(a[0]), "r"(a[1]), "r"(a[2]), "r"(a[3]), "r"(b0), "r"(b1));
}

__global__ __launch_bounds__(256) void mlp_kernel(
    const float* __restrict__ b1, const float* __restrict__ b2,
    float* __restrict__ out)
{
    extern __shared__ uint32_t smu[];          // [0,8704): Ah  [8704,17408): Al
    uint32_t* sAh = smu;
    uint32_t* sAl = smu + 128 * SAU;

    const int tid  = threadIdx.x;
    const int lane = tid & 31;
    const int wid  = tid >> 5;
    const int g    = lane >> 2;     // group 0..7
    const int t    = lane & 3;      // thread-in-group
    const int base = blockIdx.x * TMMLP;
    const int rowbase = wid * 16;

    // ---- load split A tile (128 x 64 u32 per split) ------------------------
    #pragma unroll 4
    for (int i = tid; i < TMMLP * 64; i += 256) {
        int row = i >> 6, cp = i & 63;
        int n = base + row;
        uint32_t vh = 0, vl = 0;
        if (n < NN) {
            vh = g_h0h[(size_t)n * 64 + cp];
            vl = g_h0l[(size_t)n * 64 + cp];
        }
        sAh[row * SAU + cp] = vh;
        sAl[row * SAU + cp] = vl;
    }
    __syncthreads();

    float c[16][4];
    const int r0 = rowbase + g;
    const int r1 = r0 + 8;

    // ================= GEMM1: relu(A@W1 + b1) -> split back to smem =========
    #pragma unroll
    for (int nt = 0; nt < 16; nt++)
        #pragma unroll
        for (int q = 0; q < 4; q++) c[nt][q] = 0.f;

    #pragma unroll 1
    for (int ks = 0; ks < 8; ks++) {
        uint32_t ah[4], al[4];
        int ai = r0 * SAU + 8 * ks + t;
        int bi = r1 * SAU + 8 * ks + t;
        ah[0] = sAh[ai];     ah[1] = sAh[bi];
        ah[2] = sAh[ai + 4]; ah[3] = sAh[bi + 4];
        al[0] = sAl[ai];     al[1] = sAl[bi];
        al[2] = sAl[ai + 4]; al[3] = sAl[bi + 4];
        #pragma unroll
        for (int nt = 0; nt < 16; nt++) {
            int wi = (nt * 8 + g) * 64 + 8 * ks + t;
            uint32_t bh0 = g_W1h[wi], bh1 = g_W1h[wi + 4];
            uint32_t bl0 = g_W1l[wi], bl1 = g_W1l[wi + 4];
            mma_bf16(c[nt], ah, bh0, bh1);
            mma_bf16(c[nt], al, bh0, bh1);
            mma_bf16(c[nt], ah, bl0, bl1);
        }
    }
    // epilogue 1 (warp-local rows; no cross-warp deps)
    #pragma unroll
    for (int nt = 0; nt < 16; nt++) {
        float2 bb = __ldg(&reinterpret_cast<const float2*>(b1)[nt * 4 + t]);
        float v0 = fmaxf(c[nt][0] + bb.x, 0.f);
        float v1 = fmaxf(c[nt][1] + bb.y, 0.f);
        float v2 = fmaxf(c[nt][2] + bb.x, 0.f);
        float v3 = fmaxf(c[nt][3] + bb.y, 0.f);
        float h0 = __bfloat162float(__float2bfloat16(v0));
        float h1 = __bfloat162float(__float2bfloat16(v1));
        float h2 = __bfloat162float(__float2bfloat16(v2));
        float h3 = __bfloat162float(__float2bfloat16(v3));
        int i0 = r0 * SAU + nt * 4 + t;
        int i1 = r1 * SAU + nt * 4 + t;
        sAh[i0] = pack2(h0, h1);
        sAh[i1] = pack2(h2, h3);
        sAl[i0] = pack2(v0 - h0, v1 - h1);
        sAl[i1] = pack2(v2 - h2, v3 - h3);
    }
    __syncwarp();

    // ================= GEMM2: h1@W2 + b2 -> out =============================
    #pragma unroll
    for (int nt = 0; nt < 16; nt++)
        #pragma unroll
        for (int q = 0; q < 4; q++) c[nt][q] = 0.f;

    #pragma unroll 1
    for (int ks = 0; ks < 8; ks++) {
        uint32_t ah[4], al[4];
        int ai = r0 * SAU + 8 * ks + t;
        int bi = r1 * SAU + 8 * ks + t;
        ah[0] = sAh[ai];     ah[1] = sAh[bi];
        ah[2] = sAh[ai + 4]; ah[3] = sAh[bi + 4];
        al[0] = sAl[ai];     al[1] = sAl[bi];
        al[2] = sAl[ai + 4]; al[3] = sAl[bi + 4];
        #pragma unroll
        for (int nt = 0; nt < 16; nt++) {
            int wi = (nt * 8 + g) * 64 + 8 * ks + t;
            uint32_t bh0 = g_W2h[wi], bh1 = g_W2h[wi + 4];
            uint32_t bl0 = g_W2l[wi], bl1 = g_W2l[wi + 4];
            mma_bf16(c[nt], ah, bh0, bh1);
            mma_bf16(c[nt], al, bh0, bh1);
            mma_bf16(c[nt], ah, bl0, bl1);
        }
    }
    // epilogue 2: bias + store (float2 per reg-pair)
    {
        int n0 = base + r0;
        int n1 = base + r1;
        float2* out2 = reinterpret_cast<float2*>(out);
        #pragma unroll
        for (int nt = 0; nt < 16; nt++) {
            float2 bb = __ldg(&reinterpret_cast<const float2*>(b2)[nt * 4 + t]);
            if (n0 < NN)
                out2[(size_t)n0 * 64 + nt * 4 + t] =
                    make_float2(c[nt][0] + bb.x, c[nt][1] + bb.y);
            if (n1 < NN)
                out2[(size_t)n1 * 64 + nt * 4 + t] =
                    make_float2(c[nt][2] + bb.x, c[nt][3] + bb.y);
        }
    }
}

// ---------------------------------------------------------------------------
extern "C" void kernel_launch(void* const* d_in, const int* in_sizes, int n_in,
                              void* d_out, int out_size) {
    const float* hidden = (const float*)d_in[0];
    const int*   ei     = (const int*)d_in[1];
    const float* ea     = (const float*)d_in[2];
    const float* We     = (const float*)d_in[3];
    const float* be     = (const float*)d_in[4];
    const float* W1     = (const float*)d_in[5];
    const float* b1     = (const float*)d_in[6];
    const float* W2     = (const float*)d_in[7];
    const float* b2     = (const float*)d_in[8];
    const float* eps    = (const float*)d_in[9];
    float* out = (float*)d_out;

    const int mlp_smem = 2 * 128 * SAU * 4;   // 69632 B
    cudaFuncSetAttribute(mlp_kernel, cudaFuncAttributeMaxDynamicSharedMemorySize,
                         mlp_smem);

    zero_kernel<<<(NN + 255) / 256, 256>>>();
    hist_kernel<<<(EE + 255) / 256, 256>>>(ei);
    scan_kernel<<<1, 1024>>>();
    fill_kernel<<<(EE + 255) / 256, 256>>>(ei, ea);
    wsplit_kernel<<<(DD * 64 + 255) / 256, 256>>>(W1, W2);
    agg_kernel<<<(NN + TMAGG - 1) / TMAGG, 256>>>(hidden, We, be, eps);
    mlp_kernel<<<(NN + TMMLP - 1) / TMMLP, 256, mlp_smem>>>(b1, b2, out);
}

// round 16
// speedup vs baseline: 1.0151x; 1.0151x over previous
#include <cuda_runtime.h>
#include <cuda_bf16.h>
#include <cstdint>

#define NN 50000
#define EE 800000
#define DD 128
#define TMROWS 128               // nodes per block, fused kernel
#define SAU 68                   // smem A row stride in u32 (136 bf16)

// ---- scratch (__device__ globals) -----------------------------------------
__device__ int  g_deg[NN];
__device__ int  g_cursor[NN];
__device__ int  g_off[NN + 1];
__device__ int2 g_edge[EE];                    // (src, attr bits)
__device__ uint32_t g_W1h[DD * 64], g_W1l[DD * 64];   // Wt[n][k] bf16x2 k-pairs
__device__ uint32_t g_W2h[DD * 64], g_W2l[DD * 64];

// ---------------------------------------------------------------------------
__global__ void zero_kernel() {
    int i = blockIdx.x * blockDim.x + threadIdx.x;
    if (i < NN) g_deg[i] = 0;
}

// 4 edges per thread (int4 loads) — MLP=4 hides LDG->atomic chain
__global__ __launch_bounds__(256) void hist_kernel(const int* __restrict__ ei) {
    int t = blockIdx.x * blockDim.x + threadIdx.x;
    if (t >= EE / 4) return;
    int4 d = __ldg(&reinterpret_cast<const int4*>(ei + EE)[t]);
    atomicAdd(&g_deg[d.x], 1);
    atomicAdd(&g_deg[d.y], 1);
    atomicAdd(&g_deg[d.z], 1);
    atomicAdd(&g_deg[d.w], 1);
}

__global__ __launch_bounds__(1024) void scan_kernel() {
    __shared__ int wsum[32];
    __shared__ int carry_sh;
    const int lane = threadIdx.x & 31;
    const int wid  = threadIdx.x >> 5;
    if (threadIdx.x == 0) carry_sh = 0;
    __syncthreads();
    for (int base = 0; base < NN; base += 1024) {
        int i = base + threadIdx.x;
        int v = (i < NN) ? g_deg[i] : 0;
        int orig = v;
        #pragma unroll
        for (int off = 1; off < 32; off <<= 1) {
            int t = __shfl_up_sync(0xffffffffu, v, off);
            if (lane >= off) v += t;
        }
        if (lane == 31) wsum[wid] = v;
        __syncthreads();
        if (wid == 0) {
            int s = wsum[lane];
            #pragma unroll
            for (int off = 1; off < 32; off <<= 1) {
                int t = __shfl_up_sync(0xffffffffu, s, off);
                if (lane >= off) s += t;
            }
            wsum[lane] = s;
        }
        __syncthreads();
        int warp_prefix = (wid > 0) ? wsum[wid - 1] : 0;
        int carry = carry_sh;
        if (i < NN) {
            int excl = carry + warp_prefix + v - orig;
            g_off[i] = excl;
            g_cursor[i] = excl;
        }
        __syncthreads();
        if (threadIdx.x == 1023) carry_sh = carry + wsum[31];
        __syncthreads();
    }
    if (threadIdx.x == 0) g_off[NN] = carry_sh;
}

__global__ __launch_bounds__(256) void fill_kernel(
    const int* __restrict__ ei, const float* __restrict__ ea)
{
    int t = blockIdx.x * blockDim.x + threadIdx.x;
    if (t >= EE / 4) return;
    int4   s = __ldg(&reinterpret_cast<const int4*>(ei)[t]);
    int4   d = __ldg(&reinterpret_cast<const int4*>(ei + EE)[t]);
    float4 a = __ldg(&reinterpret_cast<const float4*>(ea)[t]);
    g_edge[atomicAdd(&g_cursor[d.x], 1)] = make_int2(s.x, __float_as_int(a.x));
    g_edge[atomicAdd(&g_cursor[d.y], 1)] = make_int2(s.y, __float_as_int(a.y));
    g_edge[atomicAdd(&g_cursor[d.z], 1)] = make_int2(s.z, __float_as_int(a.z));
    g_edge[atomicAdd(&g_cursor[d.w], 1)] = make_int2(s.w, __float_as_int(a.w));
}

// ---------------------------------------------------------------------------
__device__ __forceinline__ uint32_t pack2(float a, float b) {
    __nv_bfloat16 ha = __float2bfloat16(a), hb = __float2bfloat16(b);
    return ((uint32_t)__bfloat16_as_ushort(hb) << 16) | __bfloat16_as_ushort(ha);
}

__global__ __launch_bounds__(256) void wsplit_kernel(
    const float* __restrict__ W1, const float* __restrict__ W2)
{
    int i = blockIdx.x * blockDim.x + threadIdx.x;   // 8192 k-pairs
    if (i >= DD * 64) return;
    int n = i >> 6;
    int k = (i & 63) * 2;
    float a0 = __ldg(&W1[(size_t)k * DD + n]);
    float a1 = __ldg(&W1[(size_t)(k + 1) * DD + n]);
    float b0 = __ldg(&W2[(size_t)k * DD + n]);
    float b1 = __ldg(&W2[(size_t)(k + 1) * DD + n]);
    float ah0 = __bfloat162float(__float2bfloat16(a0));
    float ah1 = __bfloat162float(__float2bfloat16(a1));
    float bh0 = __bfloat162float(__float2bfloat16(b0));
    float bh1 = __bfloat162float(__float2bfloat16(b1));
    g_W1h[i] = pack2(ah0, ah1);
    g_W1l[i] = pack2(a0 - ah0, a1 - ah1);
    g_W2h[i] = pack2(bh0, bh1);
    g_W2l[i] = pack2(b0 - bh0, b1 - bh1);
}

// ---------------------------------------------------------------------------
// Fused: CSR gather-aggregate -> smem bf16 split -> HMMA GEMM1 -> relu ->
// HMMA GEMM2 -> out.  512 threads = 16 warps, 128 nodes/CTA.
// Gather: warp-per-node, 8 nodes/warp.  GEMM: warp pair splits N halves.
// ---------------------------------------------------------------------------
__device__ __forceinline__ void mma_bf16(float* c, const uint32_t* a,
                                         uint32_t b0, uint32_t b1) {
    asm volatile(
        "mma.sync.aligned.m16n8k16.row.col.f32.bf16.bf16.f32 "
        "{%0,%1,%2,%3}, {%4,%5,%6,%7}, {%8,%9}, {%0,%1,%2,%3};"
        : "+f"(c[0]), "+f"(c[1]), "+f"(c[2]), "+f"(c[3])
        : "r"(a[0]), "r"(a[1]), "r"(a[2]), "r"(a[3]), "r"(b0), "r"(b1));
}

__global__ __launch_bounds__(512, 2) void fused_kernel(
    const float* __restrict__ hidden,
    const float* __restrict__ We, const float* __restrict__ be,
    const float* __restrict__ b1, const float* __restrict__ b2,
    const float* __restrict__ eps,
    float* __restrict__ out)
{
    extern __shared__ uint32_t smu[];          // [0,8704): Ah  [8704,17408): Al
    uint32_t* sAh = smu;
    uint32_t* sAl = smu + 128 * SAU;

    const int tid  = threadIdx.x;
    const int lane = tid & 31;
    const int wid  = tid >> 5;          // 16 warps
    const int base = blockIdx.x * TMROWS;
    const float epsv = 1.0f + __ldg(eps);

    // ---- Stage A: gather-aggregate, warp-per-node, split into smem ---------
    {
        const float4* h4 = reinterpret_cast<const float4*>(hidden);
        float4 w = __ldg(&reinterpret_cast<const float4*>(We)[lane]);
        float4 b = __ldg(&reinterpret_cast<const float4*>(be)[lane]);
        #pragma unroll 1
        for (int j = 0; j < 8; j++) {
            int row = wid * 8 + j;
            int n = base + row;
            float4 v = make_float4(0.f, 0.f, 0.f, 0.f);
            if (n < NN) {
                int s0 = __ldg(&g_off[n]);
                int s1 = __ldg(&g_off[n + 1]);
                float4 acc = make_float4(0.f, 0.f, 0.f, 0.f);
                #pragma unroll 4
                for (int s = s0; s < s1; s++) {
                    int2 e = __ldg(&g_edge[s]);
                    float a = __int_as_float(e.y);
                    float4 h = __ldg(&h4[(size_t)e.x * 32 + lane]);
                    acc.x += fmaxf(h.x + fmaf(a, w.x, b.x), 0.f);
                    acc.y += fmaxf(h.y + fmaf(a, w.y, b.y), 0.f);
                    acc.z += fmaxf(h.z + fmaf(a, w.z, b.z), 0.f);
                    acc.w += fmaxf(h.w + fmaf(a, w.w, b.w), 0.f);
                }
                float inv = 1.0f / fmaxf((float)(s1 - s0), 1.0f);
                float4 hv = __ldg(&h4[(size_t)n * 32 + lane]);
                v.x = fmaf(epsv, hv.x, acc.x * inv);
                v.y = fmaf(epsv, hv.y, acc.y * inv);
                v.z = fmaf(epsv, hv.z, acc.z * inv);
                v.w = fmaf(epsv, hv.w, acc.w * inv);
            }
            float hx = __bfloat162float(__float2bfloat16(v.x));
            float hy = __bfloat162float(__float2bfloat16(v.y));
            float hz = __bfloat162float(__float2bfloat16(v.z));
            float hw = __bfloat162float(__float2bfloat16(v.w));
            int o = row * SAU + 2 * lane;
            sAh[o]     = pack2(hx, hy);
            sAh[o + 1] = pack2(hz, hw);
            sAl[o]     = pack2(v.x - hx, v.y - hy);
            sAl[o + 1] = pack2(v.z - hz, v.w - hw);
        }
    }
    __syncthreads();

    // ---- GEMM setup: warp pair (wp,wn): rows wp*16..+16, n-half wn ---------
    const int g  = lane >> 2;          // 0..7
    const int t  = lane & 3;           // 0..3
    const int wp = wid >> 1;           // row tile 0..7
    const int wn = wid & 1;            // n half
    const int r0 = wp * 16 + g;
    const int r1 = r0 + 8;

    float c[8][4];

    // ================= GEMM1: relu(A@W1 + b1) -> split back to smem =========
    #pragma unroll
    for (int q = 0; q < 8; q++) {
        c[q][0] = 0.f; c[q][1] = 0.f; c[q][2] = 0.f; c[q][3] = 0.f;
    }
    #pragma unroll 1
    for (int ks = 0; ks < 8; ks++) {
        uint32_t ah[4], al[4];
        int ai = r0 * SAU + 8 * ks + t;
        int bi = r1 * SAU + 8 * ks + t;
        ah[0] = sAh[ai];     ah[1] = sAh[bi];
        ah[2] = sAh[ai + 4]; ah[3] = sAh[bi + 4];
        al[0] = sAl[ai];     al[1] = sAl[bi];
        al[2] = sAl[ai + 4]; al[3] = sAl[bi + 4];
        #pragma unroll
        for (int q = 0; q < 8; q++) {
            int nt = wn * 8 + q;
            int wi = (nt * 8 + g) * 64 + 8 * ks + t;
            uint32_t bh0 = g_W1h[wi], bh1 = g_W1h[wi + 4];
            uint32_t bl0 = g_W1l[wi], bl1 = g_W1l[wi + 4];
            mma_bf16(c[q], ah, bh0, bh1);
            mma_bf16(c[q], al, bh0, bh1);
            mma_bf16(c[q], ah, bl0, bl1);
        }
    }
    __syncthreads();   // A reads done before overwrite
    #pragma unroll
    for (int q = 0; q < 8; q++) {
        int nt = wn * 8 + q;
        float2 bb = __ldg(&reinterpret_cast<const float2*>(b1)[nt * 4 + t]);
        float v0 = fmaxf(c[q][0] + bb.x, 0.f);
        float v1 = fmaxf(c[q][1] + bb.y, 0.f);
        float v2 = fmaxf(c[q][2] + bb.x, 0.f);
        float v3 = fmaxf(c[q][3] + bb.y, 0.f);
        float h0 = __bfloat162float(__float2bfloat16(v0));
        float h1 = __bfloat162float(__float2bfloat16(v1));
        float h2 = __bfloat162float(__float2bfloat16(v2));
        float h3 = __bfloat162float(__float2bfloat16(v3));
        int i0 = r0 * SAU + nt * 4 + t;
        int i1 = r1 * SAU + nt * 4 + t;
        sAh[i0] = pack2(h0, h1);
        sAh[i1] = pack2(h2, h3);
        sAl[i0] = pack2(v0 - h0, v1 - h1);
        sAl[i1] = pack2(v2 - h2, v3 - h3);
    }
    __syncthreads();   // h1 halves from both warps of the pair visible

    // ================= GEMM2: h1@W2 + b2 -> out =============================
    #pragma unroll
    for (int q = 0; q < 8; q++) {
        c[q][0] = 0.f; c[q][1] = 0.f; c[q][2] = 0.f; c[q][3] = 0.f;
    }
    #pragma unroll 1
    for (int ks = 0; ks < 8; ks++) {
        uint32_t ah[4], al[4];
        int ai = r0 * SAU + 8 * ks + t;
        int bi = r1 * SAU + 8 * ks + t;
        ah[0] = sAh[ai];     ah[1] = sAh[bi];
        ah[2] = sAh[ai + 4]; ah[3] = sAh[bi + 4];
        al[0] = sAl[ai];     al[1] = sAl[bi];
        al[2] = sAl[ai + 4]; al[3] = sAl[bi + 4];
        #pragma unroll
        for (int q = 0; q < 8; q++) {
            int nt = wn * 8 + q;
            int wi = (nt * 8 + g) * 64 + 8 * ks + t;
            uint32_t bh0 = g_W2h[wi], bh1 = g_W2h[wi + 4];
            uint32_t bl0 = g_W2l[wi], bl1 = g_W2l[wi + 4];
            mma_bf16(c[q], ah, bh0, bh1);
            mma_bf16(c[q], al, bh0, bh1);
            mma_bf16(c[q], ah, bl0, bl1);
        }
    }
    {
        int n0 = base + r0;
        int n1 = base + r1;
        float2* out2 = reinterpret_cast<float2*>(out);
        #pragma unroll
        for (int q = 0; q < 8; q++) {
            int nt = wn * 8 + q;
            float2 bb = __ldg(&reinterpret_cast<const float2*>(b2)[nt * 4 + t]);
            if (n0 < NN)
                out2[(size_t)n0 * 64 + nt * 4 + t] =
                    make_float2(c[q][0] + bb.x, c[q][1] + bb.y);
            if (n1 < NN)
                out2[(size_t)n1 * 64 + nt * 4 + t] =
                    make_float2(c[q][2] + bb.x, c[q][3] + bb.y);
        }
    }
}

// ---------------------------------------------------------------------------
extern "C" void kernel_launch(void* const* d_in, const int* in_sizes, int n_in,
                              void* d_out, int out_size) {
    const float* hidden = (const float*)d_in[0];
    const int*   ei     = (const int*)d_in[1];
    const float* ea     = (const float*)d_in[2];
    const float* We     = (const float*)d_in[3];
    const float* be     = (const float*)d_in[4];
    const float* W1     = (const float*)d_in[5];
    const float* b1     = (const float*)d_in[6];
    const float* W2     = (const float*)d_in[7];
    const float* b2     = (const float*)d_in[8];
    const float* eps    = (const float*)d_in[9];
    float* out = (float*)d_out;

    const int fused_smem = 2 * 128 * SAU * 4;   // 69632 B
    cudaFuncSetAttribute(fused_kernel, cudaFuncAttributeMaxDynamicSharedMemorySize,
                         fused_smem);

    zero_kernel<<<(NN + 255) / 256, 256>>>();
    hist_kernel<<<(EE / 4 + 255) / 256, 256>>>(ei);
    scan_kernel<<<1, 1024>>>();
    fill_kernel<<<(EE / 4 + 255) / 256, 256>>>(ei, ea);
    wsplit_kernel<<<(DD * 64 + 255) / 256, 256>>>(W1, W2);
    fused_kernel<<<(NN + TMROWS - 1) / TMROWS, 512, fused_smem>>>(
        hidden, We, be, b1, b2, eps, out);
}